// round 2
// baseline (speedup 1.0000x reference)
#include <cuda_runtime.h>
#include <cstdint>

// Masked cumsum along dim 1: out[b, :] = cumsum(where(mask, x, 0))
// B=256 rows, N=131072 cols, fp32 x, **int32 mask** (harness materializes
// jnp.bool_ as int32 — R1's byte-mask read was the 0.99 rel_err).
//
// One CTA per row. 512 threads x 8 elems/thread = 4096-elem chunks, 32 chunks
// per row. Per chunk: thread-serial scan -> warp shfl scan -> cross-warp smem
// scan -> add running carry -> vectorized store. One-chunk-ahead register
// prefetch overlaps DRAM latency with the scan; double-buffered smem keeps it
// to 2 barriers per chunk.

#define CS_THREADS 512
#define CS_VPT     8
#define CS_CHUNK   (CS_THREADS * CS_VPT)      // 4096
#define CS_NCOLS   131072
#define CS_ITERS   (CS_NCOLS / CS_CHUNK)      // 32
#define CS_NWARPS  (CS_THREADS / 32)          // 16

__global__ __launch_bounds__(CS_THREADS, 2)
void masked_cumsum_kernel(const float* __restrict__ x,
                          const int* __restrict__ mask,
                          float* __restrict__ out) {
    __shared__ float sh[2][CS_NWARPS + 1];  // [buf][0..15]=warp excl prefix, [16]=chunk total

    const int row = blockIdx.x;
    const size_t roff = (size_t)row * CS_NCOLS;
    const float4* __restrict__ x4 = reinterpret_cast<const float4*>(x + roff);
    const int4*   __restrict__ m4 = reinterpret_cast<const int4*>(mask + roff);
    float4* __restrict__ o4 = reinterpret_cast<float4*>(out + roff);

    const int tid  = threadIdx.x;
    const int lane = tid & 31;
    const int warp = tid >> 5;

    float carry = 0.0f;

    // Prefetch chunk 0 (8 contiguous elems per thread: 2x float4, 2x int4 mask)
    float4 pa = x4[tid * 2];
    float4 pb = x4[tid * 2 + 1];
    int4   pma = m4[tid * 2];
    int4   pmb = m4[tid * 2 + 1];

    for (int it = 0; it < CS_ITERS; ++it) {
        float4 xa = pa, xb = pb;
        int4   ma = pma, mb = pmb;
        // Issue next chunk's loads immediately; consumed next iteration.
        if (it + 1 < CS_ITERS) {
            const int b4 = (it + 1) * (CS_CHUNK / 4) + tid * 2;
            pa  = x4[b4];
            pb  = x4[b4 + 1];
            pma = m4[b4];
            pmb = m4[b4 + 1];
        }

        // Apply mask (each int32 is 0 or 1)
        float v[CS_VPT];
        v[0] = ma.x ? xa.x : 0.0f;
        v[1] = ma.y ? xa.y : 0.0f;
        v[2] = ma.z ? xa.z : 0.0f;
        v[3] = ma.w ? xa.w : 0.0f;
        v[4] = mb.x ? xb.x : 0.0f;
        v[5] = mb.y ? xb.y : 0.0f;
        v[6] = mb.z ? xb.z : 0.0f;
        v[7] = mb.w ? xb.w : 0.0f;

        // Thread-local inclusive scan
        #pragma unroll
        for (int i = 1; i < CS_VPT; ++i) v[i] += v[i - 1];
        const float tsum = v[CS_VPT - 1];

        // Warp inclusive scan of per-thread sums
        float s = tsum;
        #pragma unroll
        for (int d = 1; d < 32; d <<= 1) {
            float n = __shfl_up_sync(0xffffffffu, s, d);
            if (lane >= d) s += n;
        }

        const int buf = it & 1;
        if (lane == 31) sh[buf][warp] = s;
        __syncthreads();

        // Warp 0 scans the 16 warp totals
        if (warp == 0) {
            float w = (lane < CS_NWARPS) ? sh[buf][lane] : 0.0f;
            float ws = w;
            #pragma unroll
            for (int d = 1; d < 32; d <<= 1) {
                float n = __shfl_up_sync(0xffffffffu, ws, d);
                if (lane >= d) ws += n;
            }
            if (lane < CS_NWARPS)      sh[buf][lane]      = ws - w;  // exclusive warp prefix
            if (lane == CS_NWARPS - 1) sh[buf][CS_NWARPS] = ws;      // chunk total
        }
        __syncthreads();

        const float base = carry + sh[buf][warp] + (s - tsum);
        carry += sh[buf][CS_NWARPS];

        const float4 oa = make_float4(v[0] + base, v[1] + base, v[2] + base, v[3] + base);
        const float4 ob = make_float4(v[4] + base, v[5] + base, v[6] + base, v[7] + base);
        const int b4 = it * (CS_CHUNK / 4) + tid * 2;
        o4[b4]     = oa;
        o4[b4 + 1] = ob;
        // No trailing barrier needed: next iteration writes the other smem buffer.
    }
}

extern "C" void kernel_launch(void* const* d_in, const int* in_sizes, int n_in,
                              void* d_out, int out_size) {
    const float* x    = (const float*)d_in[0];
    const int*   mask = (const int*)d_in[1];
    float*       out  = (float*)d_out;
    const int rows = out_size / CS_NCOLS;   // 256
    masked_cumsum_kernel<<<rows, CS_THREADS>>>(x, mask, out);
}